// round 1
// baseline (speedup 1.0000x reference)
#include <cuda_runtime.h>
#include <math.h>

#define T_HRZ 1024
#define NB    128
#define NU    64
#define NY    64
#define NH    256
#define NPAIR 128
#define NCHUNK 16
#define LCHUNK 64   /* 1024/16 */

// ---------------- scratch (static __device__ arrays: no allocation) ----------
__device__ float  g_Bu[(size_t)T_HRZ * NB * NH];   // 128 MB
__device__ float  g_X [(size_t)T_HRZ * NB * NH];   // 128 MB
__device__ float2 g_F [NCHUNK * NB * NPAIR];       // chunk-local finals
__device__ float2 g_S [NCHUNK * NB * NPAIR];       // true chunk-initial states
__device__ float  g_lr[NPAIR];
__device__ float  g_li[NPAIR];
__device__ float  g_nf[NH];
__device__ float2 g_lamL[NPAIR];                   // lambda^LCHUNK

// ---------------- K0: derived parameters ------------------------------------
__global__ void params_kernel(const float* __restrict__ lrc,
                              const float* __restrict__ lic) {
    int j = threadIdx.x;
    if (j < NPAIR) {
        float a  = fabsf(lrc[j]);
        float r  = expf(-a);
        float th = 1.5707963267948966f * lic[j];
        float lr = r * cosf(th);
        float li = r * sinf(th);
        float nf = sqrtf(1.0f - expf(-2.0f * a));
        g_lr[j] = lr;
        g_li[j] = li;
        g_nf[j] = nf;
        g_nf[j + NPAIR] = nf;
        float wr = 1.0f, wi = 0.0f;
        for (int l = 0; l < LCHUNK; ++l) {
            float nr = wr * lr - wi * li;
            wi       = wr * li + wi * lr;
            wr       = nr;
        }
        g_lamL[j] = make_float2(wr, wi);
    }
}

// ---------------- K1: Bu = (U @ B^T) * nf  ----------------------------------
// M = T*NB = 131072, N = NH = 256, K = NU = 64.
// Block tile 128x128, BK=32, 256 threads, 8x8 per-thread microtile.
__global__ void __launch_bounds__(256) gemm_bu(const float* __restrict__ U,
                                               const float* __restrict__ Bw) {
    __shared__ float Ast[32][132];   // [k][m]
    __shared__ float Bst[32][132];   // [k][n]
    const int tid   = threadIdx.x;
    const int mBase = blockIdx.x * 128;
    const int nBase = blockIdx.y * 128;

    float acc[8][8];
#pragma unroll
    for (int i = 0; i < 8; ++i)
#pragma unroll
        for (int j = 0; j < 8; ++j) acc[i][j] = 0.0f;

    const int ty = tid >> 4, tx = tid & 15;
    const int row0 = ty * 8, col0 = tx * 8;

#pragma unroll
    for (int kt = 0; kt < 2; ++kt) {
        // load 128x32 A and 128x32 B (transposed into smem), float4 global loads
#pragma unroll
        for (int it = 0; it < 4; ++it) {
            int v = it * 256 + tid;          // 0..1023
            int m = v >> 3, kv = v & 7;
            float4 av = *(const float4*)&U[((size_t)(mBase + m)) * NU + kt * 32 + kv * 4];
            Ast[kv * 4 + 0][m] = av.x;
            Ast[kv * 4 + 1][m] = av.y;
            Ast[kv * 4 + 2][m] = av.z;
            Ast[kv * 4 + 3][m] = av.w;
            float s = g_nf[nBase + m];       // m doubles as n here
            float4 bv = *(const float4*)&Bw[((size_t)(nBase + m)) * NU + kt * 32 + kv * 4];
            Bst[kv * 4 + 0][m] = bv.x * s;
            Bst[kv * 4 + 1][m] = bv.y * s;
            Bst[kv * 4 + 2][m] = bv.z * s;
            Bst[kv * 4 + 3][m] = bv.w * s;
        }
        __syncthreads();
#pragma unroll
        for (int k = 0; k < 32; ++k) {
            float4 a0 = *(const float4*)&Ast[k][row0];
            float4 a1 = *(const float4*)&Ast[k][row0 + 4];
            float4 b0 = *(const float4*)&Bst[k][col0];
            float4 b1 = *(const float4*)&Bst[k][col0 + 4];
            float a[8] = {a0.x, a0.y, a0.z, a0.w, a1.x, a1.y, a1.z, a1.w};
            float b[8] = {b0.x, b0.y, b0.z, b0.w, b1.x, b1.y, b1.z, b1.w};
#pragma unroll
            for (int i = 0; i < 8; ++i)
#pragma unroll
                for (int j = 0; j < 8; ++j)
                    acc[i][j] = fmaf(a[i], b[j], acc[i][j]);
        }
        __syncthreads();
    }

#pragma unroll
    for (int i = 0; i < 8; ++i) {
        size_t row = (size_t)(mBase + row0 + i);
        *(float4*)&g_Bu[row * NH + nBase + col0] =
            make_float4(acc[i][0], acc[i][1], acc[i][2], acc[i][3]);
        *(float4*)&g_Bu[row * NH + nBase + col0 + 4] =
            make_float4(acc[i][4], acc[i][5], acc[i][6], acc[i][7]);
    }
}

// ---------------- K2: blocked scan (pass A: finals only; pass B: write X) ----
template <bool WRITE_X, bool PASS_B>
__global__ void __launch_bounds__(256) scan_kernel() {
    int gtid = blockIdx.x * 256 + threadIdx.x;   // < NCHUNK*NB*NPAIR
    int j = gtid & (NPAIR - 1);
    int b = (gtid >> 7) & (NB - 1);
    int c = gtid >> 14;

    float ar = g_lr[j], ai = g_li[j];
    float xr, xi;
    if (PASS_B) {
        float2 s = g_S[(c * NB + b) * NPAIR + j];
        xr = s.x; xi = s.y;
    } else {
        xr = 0.0f; xi = 0.0f;
    }

    size_t base = ((size_t)(c * LCHUNK) * NB + b) * NH + j;
#pragma unroll 8
    for (int l = 0; l < LCHUNK; ++l) {
        float bur = g_Bu[base];
        float bui = g_Bu[base + NPAIR];
        float nr = fmaf(ar, xr, fmaf(-ai, xi, bur));
        float ni = fmaf(ai, xr, fmaf(ar, xi, bui));
        xr = nr; xi = ni;
        if (WRITE_X) {
            g_X[base]         = xr;
            g_X[base + NPAIR] = xi;
        }
        base += (size_t)NB * NH;
    }
    if (!PASS_B) g_F[(c * NB + b) * NPAIR + j] = make_float2(xr, xi);
}

// ---------------- K3: carry scan across chunks (+ x0 matvec) -----------------
__global__ void __launch_bounds__(256) carry_kernel(const float* __restrict__ y0,
                                                    const float* __restrict__ Wy2x,
                                                    const float* __restrict__ by2x) {
    int gtid = blockIdx.x * 256 + threadIdx.x;   // < NB*NPAIR = 16384
    int j = gtid & (NPAIR - 1);
    int b = gtid >> 7;

    // x0[b, j] and x0[b, j+128]
    float xr = by2x[j];
    float xi = by2x[j + NPAIR];
    const float* yrow = y0 + (size_t)b * NY;
    const float* w1 = Wy2x + (size_t)j * NY;
    const float* w2 = Wy2x + (size_t)(j + NPAIR) * NY;
#pragma unroll
    for (int y = 0; y < NY; ++y) {
        float yv = yrow[y];
        xr = fmaf(yv, w1[y], xr);
        xi = fmaf(yv, w2[y], xi);
    }
    g_S[b * NPAIR + j] = make_float2(xr, xi);    // S[0] = x0

    float2 w = g_lamL[j];
    for (int c = 1; c < NCHUNK; ++c) {
        float2 f = g_F[((c - 1) * NB + b) * NPAIR + j];
        float nr = fmaf(w.x, xr, fmaf(-w.y, xi, f.x));
        float ni = fmaf(w.y, xr, fmaf(w.x, xi, f.y));
        xr = nr; xi = ni;
        g_S[(c * NB + b) * NPAIR + j] = make_float2(xr, xi);
    }
}

// ---------------- K4: Y = X @ W_x2y^T + b ------------------------------------
// M = 131072, N = 64, K = 256. Block tile 128x64, BK=32, 8x4 per-thread.
__global__ void __launch_bounds__(256) gemm_y(const float* __restrict__ W,
                                              const float* __restrict__ bias,
                                              float* __restrict__ Y) {
    __shared__ float Ast[32][132];   // [k][m]
    __shared__ float Bst[32][68];    // [k][n]
    const int tid = threadIdx.x;
    const size_t mBase = (size_t)blockIdx.x * 128;

    float acc[8][4];
#pragma unroll
    for (int i = 0; i < 8; ++i)
#pragma unroll
        for (int j = 0; j < 4; ++j) acc[i][j] = 0.0f;

    const int ty = tid >> 4, tx = tid & 15;
    const int row0 = ty * 8, col0 = tx * 4;

#pragma unroll 1
    for (int kt = 0; kt < 8; ++kt) {
#pragma unroll
        for (int it = 0; it < 4; ++it) {
            int v = it * 256 + tid;          // 0..1023
            int m = v >> 3, kv = v & 7;
            float4 av = *(const float4*)&g_X[(mBase + m) * NH + kt * 32 + kv * 4];
            Ast[kv * 4 + 0][m] = av.x;
            Ast[kv * 4 + 1][m] = av.y;
            Ast[kv * 4 + 2][m] = av.z;
            Ast[kv * 4 + 3][m] = av.w;
        }
#pragma unroll
        for (int it = 0; it < 2; ++it) {
            int v = it * 256 + tid;          // 0..511
            int n = v >> 3, kv = v & 7;
            float4 bv = *(const float4*)&W[(size_t)n * NH + kt * 32 + kv * 4];
            Bst[kv * 4 + 0][n] = bv.x;
            Bst[kv * 4 + 1][n] = bv.y;
            Bst[kv * 4 + 2][n] = bv.z;
            Bst[kv * 4 + 3][n] = bv.w;
        }
        __syncthreads();
#pragma unroll
        for (int k = 0; k < 32; ++k) {
            float4 a0 = *(const float4*)&Ast[k][row0];
            float4 a1 = *(const float4*)&Ast[k][row0 + 4];
            float4 bv = *(const float4*)&Bst[k][col0];
            float a[8] = {a0.x, a0.y, a0.z, a0.w, a1.x, a1.y, a1.z, a1.w};
            float b[4] = {bv.x, bv.y, bv.z, bv.w};
#pragma unroll
            for (int i = 0; i < 8; ++i)
#pragma unroll
                for (int j = 0; j < 4; ++j)
                    acc[i][j] = fmaf(a[i], b[j], acc[i][j]);
        }
        __syncthreads();
    }

    float4 bj = *(const float4*)&bias[col0];
#pragma unroll
    for (int i = 0; i < 8; ++i) {
        size_t row = mBase + row0 + i;
        *(float4*)&Y[row * NY + col0] =
            make_float4(acc[i][0] + bj.x, acc[i][1] + bj.y,
                        acc[i][2] + bj.z, acc[i][3] + bj.w);
    }
}

// ---------------- launch ------------------------------------------------------
extern "C" void kernel_launch(void* const* d_in, const int* in_sizes, int n_in,
                              void* d_out, int out_size) {
    const float* y0   = (const float*)d_in[0];
    const float* U    = (const float*)d_in[1];
    const float* lrc  = (const float*)d_in[2];
    const float* lic  = (const float*)d_in[3];
    const float* B    = (const float*)d_in[4];
    const float* Wy2x = (const float*)d_in[5];
    const float* by2x = (const float*)d_in[6];
    const float* Wx2y = (const float*)d_in[7];
    const float* bx2y = (const float*)d_in[8];
    float* Y = (float*)d_out;

    params_kernel<<<1, 128>>>(lrc, lic);

    dim3 g1(T_HRZ * NB / 128, NH / 128);
    gemm_bu<<<g1, 256>>>(U, B);

    scan_kernel<false, false><<<NCHUNK * NB * NPAIR / 256, 256>>>();

    carry_kernel<<<NB * NPAIR / 256, 256>>>(y0, Wy2x, by2x);

    scan_kernel<true, true><<<NCHUNK * NB * NPAIR / 256, 256>>>();

    gemm_y<<<T_HRZ * NB / 128, 256>>>(Wx2y, bx2y, Y);
}

// round 3
// speedup vs baseline: 1.6046x; 1.6046x over previous
#include <cuda_runtime.h>
#include <cuda_bf16.h>
#include <cstdint>
#include <math.h>

#define T_HRZ 1024
#define NB    128
#define NU    64
#define NY    64
#define NH    256
#define NPAIR 128
#define NCHUNK 16
#define LCHUNK 64

// ---------------- scratch (static device arrays) -----------------------------
__device__ float  g_Bu[(size_t)T_HRZ * NB * NH];   // 128 MB
__device__ float  g_X [(size_t)T_HRZ * NB * NH];   // 128 MB
__device__ float2 g_F [NCHUNK * NB * NPAIR];
__device__ float2 g_S [NCHUNK * NB * NPAIR];
__device__ float  g_lr[NPAIR], g_li[NPAIR], g_nf[NH];
__device__ float2 g_lamL[NPAIR];
__device__ uint16_t g_B1h[NH * NU], g_B1l[NH * NU];    // nf-scaled B, bf16 hi/lo, [n][k]
__device__ uint16_t g_W2h[NY * NH], g_W2l[NY * NH];    // Wx2y bf16 hi/lo, [n][k]

// ---------------- helpers ----------------------------------------------------
__device__ __forceinline__ void cvt_hilo(float f, uint16_t& h, uint16_t& l) {
    __nv_bfloat16 hb = __float2bfloat16(f);
    float fh = __bfloat162float(hb);
    __nv_bfloat16 lb = __float2bfloat16(f - fh);
    h = __bfloat16_as_ushort(hb);
    l = __bfloat16_as_ushort(lb);
}

__device__ __forceinline__ uint32_t lds32(const uint16_t* p) {
    return *(const uint32_t*)p;
}

__device__ __forceinline__ void mma16816(float* c, const uint32_t* a,
                                         uint32_t b0, uint32_t b1) {
    asm volatile(
        "mma.sync.aligned.m16n8k16.row.col.f32.bf16.bf16.f32 "
        "{%0,%1,%2,%3}, {%4,%5,%6,%7}, {%8,%9}, {%0,%1,%2,%3};"
        : "+f"(c[0]), "+f"(c[1]), "+f"(c[2]), "+f"(c[3])
        : "r"(a[0]), "r"(a[1]), "r"(a[2]), "r"(a[3]), "r"(b0), "r"(b1));
}

// ---------------- K0: params --------------------------------------------------
__global__ void params_kernel(const float* __restrict__ lrc, const float* __restrict__ lic) {
    int j = threadIdx.x;
    if (j < NPAIR) {
        float a = fabsf(lrc[j]);
        float r = expf(-a);
        float th = 1.5707963267948966f * lic[j];
        float lr = r * cosf(th), li = r * sinf(th);
        float nf = sqrtf(1.0f - expf(-2.0f * a));
        g_lr[j] = lr; g_li[j] = li;
        g_nf[j] = nf; g_nf[j + NPAIR] = nf;
        float wr = 1.0f, wi = 0.0f;
        for (int l = 0; l < LCHUNK; ++l) {
            float nr = wr * lr - wi * li;
            wi = wr * li + wi * lr; wr = nr;
        }
        g_lamL[j] = make_float2(wr, wi);
    }
}

// ---------------- K0b: operand prep (bf16 hi/lo splits) -----------------------
__global__ void prep_kernel(const float* __restrict__ B, const float* __restrict__ W) {
    int i = blockIdx.x * 256 + threadIdx.x;
    if (i < NH * NU) {
        float v = B[i] * g_nf[i >> 6];
        cvt_hilo(v, g_B1h[i], g_B1l[i]);
    }
    if (i < NY * NH) {
        cvt_hilo(W[i], g_W2h[i], g_W2l[i]);
    }
}

// ---------------- K1: Bu GEMM (mma.sync bf16, hi/lo split) --------------------
// Block = one t: out 128x256, K=64 (x3 split passes). 512 threads, 16 warps,
// warp tile 32(m) x 64(n).
#define G1_PA 136                      // halves pitch (64 hi + 64 lo + 8 pad)
#define G1_ASZ (128 * G1_PA * 2)       // 34816 B
#define G1_BSZ (256 * G1_PA * 2)       // 69632 B
#define G1_SMEM (G1_ASZ + G1_BSZ)

__global__ void __launch_bounds__(512, 1) gemm_bu_mma(const float* __restrict__ U) {
    extern __shared__ char smem[];
    uint16_t* As = (uint16_t*)smem;
    uint16_t* Bs = (uint16_t*)(smem + G1_ASZ);
    const int tid = threadIdx.x, wid = tid >> 5, lane = tid & 31;
    const int g = lane >> 2, q = lane & 3;
    const int t = blockIdx.x;

    // fill A = U[t] (128x64 f32 -> hi/lo)
    const float4* Usrc = (const float4*)(U + (size_t)t * NB * NU);
#pragma unroll
    for (int it = 0; it < 4; ++it) {
        int i = it * 512 + tid;        // 2048 float4
        int m = i >> 4, k4 = (i & 15) * 4;
        float4 v = Usrc[i];
        uint16_t h0,l0,h1,l1,h2,l2,h3,l3;
        cvt_hilo(v.x,h0,l0); cvt_hilo(v.y,h1,l1); cvt_hilo(v.z,h2,l2); cvt_hilo(v.w,h3,l3);
        uint16_t* ap = As + m * G1_PA;
        *(uint2*)&ap[k4]      = make_uint2(h0 | ((uint32_t)h1 << 16), h2 | ((uint32_t)h3 << 16));
        *(uint2*)&ap[64 + k4] = make_uint2(l0 | ((uint32_t)l1 << 16), l2 | ((uint32_t)l3 << 16));
    }
    // fill B from preconverted bf16 (256x64 hi + lo)
#pragma unroll
    for (int it = 0; it < 4; ++it) {
        int i = it * 512 + tid;        // 2048 uint4 (8 halves each)
        int n = i >> 3, k8 = (i & 7) * 8;
        uint4 vh = ((const uint4*)g_B1h)[i];
        uint4 vl = ((const uint4*)g_B1l)[i];
        uint16_t* bp = Bs + n * G1_PA;
        *(uint4*)&bp[k8]      = vh;
        *(uint4*)&bp[64 + k8] = vl;
    }
    __syncthreads();

    const int m0 = (wid & 3) * 32, n0 = (wid >> 2) * 64;
    float c[2][8][4];
#pragma unroll
    for (int mi = 0; mi < 2; ++mi)
#pragma unroll
        for (int ni = 0; ni < 8; ++ni)
#pragma unroll
            for (int e = 0; e < 4; ++e) c[mi][ni][e] = 0.0f;

#pragma unroll
    for (int p = 0; p < 3; ++p) {
        const int ao = (p == 2) ? 64 : 0;
        const int bo = (p == 1) ? 64 : 0;
#pragma unroll
        for (int kk = 0; kk < 4; ++kk) {
            const int kb = kk * 16;
            uint32_t a[2][4];
#pragma unroll
            for (int mi = 0; mi < 2; ++mi) {
                const uint16_t* ap = As + (m0 + mi * 16 + g) * G1_PA + ao + kb + 2 * q;
                a[mi][0] = lds32(ap);
                a[mi][1] = lds32(ap + 8 * G1_PA);
                a[mi][2] = lds32(ap + 8);
                a[mi][3] = lds32(ap + 8 * G1_PA + 8);
            }
#pragma unroll
            for (int ni = 0; ni < 8; ++ni) {
                const uint16_t* bp = Bs + (n0 + ni * 8 + g) * G1_PA + bo + kb + 2 * q;
                uint32_t b0 = lds32(bp), b1 = lds32(bp + 8);
                mma16816(c[0][ni], a[0], b0, b1);
                mma16816(c[1][ni], a[1], b0, b1);
            }
        }
    }

    // epilogue: coalesced float2 stores into plain [t][m][n] layout
    float* out = g_Bu + (size_t)t * NB * NH;
#pragma unroll
    for (int mi = 0; mi < 2; ++mi) {
#pragma unroll
        for (int ni = 0; ni < 8; ++ni) {
            int r = m0 + mi * 16 + g, n = n0 + ni * 8 + 2 * q;
            *(float2*)&out[(size_t)r * NH + n]       = make_float2(c[mi][ni][0], c[mi][ni][1]);
            *(float2*)&out[(size_t)(r + 8) * NH + n] = make_float2(c[mi][ni][2], c[mi][ni][3]);
        }
    }
}

// ---------------- K2: blocked scans -------------------------------------------
template <bool PASS_B>
__global__ void __launch_bounds__(256) scan_kernel() {
    int gtid = blockIdx.x * 256 + threadIdx.x;
    int j = gtid & (NPAIR - 1);
    int b = (gtid >> 7) & (NB - 1);
    int c = gtid >> 14;
    float ar = g_lr[j], ai = g_li[j];
    float xr = 0.0f, xi = 0.0f;
    if (PASS_B) { float2 s = g_S[(c * NB + b) * NPAIR + j]; xr = s.x; xi = s.y; }
    size_t base = ((size_t)(c * LCHUNK) * NB + b) * NH + j;
#pragma unroll 8
    for (int l = 0; l < LCHUNK; ++l) {
        float bur = g_Bu[base];
        float bui = g_Bu[base + NPAIR];
        float nr = fmaf(ar, xr, fmaf(-ai, xi, bur));
        float ni = fmaf(ai, xr, fmaf(ar, xi, bui));
        xr = nr; xi = ni;
        if (PASS_B) {
            g_X[base]         = xr;
            g_X[base + NPAIR] = xi;
        }
        base += (size_t)NB * NH;
    }
    if (!PASS_B) g_F[(c * NB + b) * NPAIR + j] = make_float2(xr, xi);
}

// ---------------- K3a: x0 = y0 @ Wy2x^T + b -----------------------------------
__global__ void __launch_bounds__(128) x0_kernel(const float* __restrict__ y0,
                                                 const float* __restrict__ W,
                                                 const float* __restrict__ bias) {
    __shared__ float Ws[128 * 65];
    __shared__ float ys[64];
    int b = blockIdx.x, tid = threadIdx.x;
    if (tid < 64) ys[tid] = y0[(size_t)b * NY + tid];
    float xr = 0.0f, xi = 0.0f;
#pragma unroll
    for (int half = 0; half < 2; ++half) {
        const float4* src = (const float4*)(W + (size_t)half * 128 * NY);
        for (int i = tid; i < 2048; i += 128) {
            float4 v = src[i];
            int r = i >> 4, cc = (i & 15) * 4;
            float* d = &Ws[r * 65 + cc];
            d[0] = v.x; d[1] = v.y; d[2] = v.z; d[3] = v.w;
        }
        __syncthreads();
        float acc = bias[tid + half * 128];
        const float* w = &Ws[tid * 65];
#pragma unroll
        for (int y = 0; y < NY; ++y) acc = fmaf(ys[y], w[y], acc);
        if (half == 0) xr = acc; else xi = acc;
        __syncthreads();
    }
    g_S[b * NPAIR + tid] = make_float2(xr, xi);
}

// ---------------- K3b: carry scan ---------------------------------------------
__global__ void __launch_bounds__(256) carry_kernel() {
    int gtid = blockIdx.x * 256 + threadIdx.x;   // 16384
    int j = gtid & (NPAIR - 1);
    int b = gtid >> 7;
    float2 f[NCHUNK - 1];
#pragma unroll
    for (int c = 0; c < NCHUNK - 1; ++c) f[c] = g_F[(c * NB + b) * NPAIR + j];
    float2 s = g_S[b * NPAIR + j];
    float2 w = g_lamL[j];
    float xr = s.x, xi = s.y;
#pragma unroll
    for (int c = 1; c < NCHUNK; ++c) {
        float nr = fmaf(w.x, xr, fmaf(-w.y, xi, f[c - 1].x));
        float ni = fmaf(w.y, xr, fmaf(w.x, xi, f[c - 1].y));
        xr = nr; xi = ni;
        g_S[(c * NB + b) * NPAIR + j] = make_float2(xr, xi);
    }
}

// ---------------- K4: Y GEMM (mma.sync bf16, hi/lo split) ---------------------
// Block = one t: out 128x64, K=256 (x3 split passes). 256 threads, 8 warps,
// warp tile 32(m) x 32(n).
#define G2_PA 520                      // halves pitch (256 hi + 256 lo + 8 pad)
#define G2_ASZ (128 * G2_PA * 2)       // 133120 B
#define G2_BSZ (64 * G2_PA * 2)        // 66560 B
#define G2_SMEM (G2_ASZ + G2_BSZ)

__global__ void __launch_bounds__(256, 1) gemm_y_mma(const float* __restrict__ bias,
                                                     float* __restrict__ Y) {
    extern __shared__ char smem[];
    uint16_t* As = (uint16_t*)smem;
    uint16_t* Bs = (uint16_t*)(smem + G2_ASZ);
    const int tid = threadIdx.x, wid = tid >> 5, lane = tid & 31;
    const int g = lane >> 2, q = lane & 3;
    const int t = blockIdx.x;

    // fill A = X[t] (128x256 f32 -> hi/lo)
    const float4* Xsrc = (const float4*)(g_X + (size_t)t * NB * NH);
#pragma unroll
    for (int it = 0; it < 32; ++it) {
        int i = it * 256 + tid;        // 8192 float4
        int m = i >> 6, k4 = (i & 63) * 4;
        float4 v = Xsrc[i];
        uint16_t h0,l0,h1,l1,h2,l2,h3,l3;
        cvt_hilo(v.x,h0,l0); cvt_hilo(v.y,h1,l1); cvt_hilo(v.z,h2,l2); cvt_hilo(v.w,h3,l3);
        uint16_t* ap = As + m * G2_PA;
        *(uint2*)&ap[k4]       = make_uint2(h0 | ((uint32_t)h1 << 16), h2 | ((uint32_t)h3 << 16));
        *(uint2*)&ap[256 + k4] = make_uint2(l0 | ((uint32_t)l1 << 16), l2 | ((uint32_t)l3 << 16));
    }
    // fill B from preconverted bf16 W (64x256 hi + lo)
#pragma unroll
    for (int it = 0; it < 8; ++it) {
        int i = it * 256 + tid;        // 2048 uint4
        int n = i >> 5, k8 = (i & 31) * 8;
        uint4 vh = ((const uint4*)g_W2h)[i];
        uint4 vl = ((const uint4*)g_W2l)[i];
        uint16_t* bp = Bs + n * G2_PA;
        *(uint4*)&bp[k8]       = vh;
        *(uint4*)&bp[256 + k8] = vl;
    }
    __syncthreads();

    const int m0 = (wid & 3) * 32, n0 = (wid >> 2) * 32;
    float c[2][4][4];
#pragma unroll
    for (int mi = 0; mi < 2; ++mi)
#pragma unroll
        for (int ni = 0; ni < 4; ++ni)
#pragma unroll
            for (int e = 0; e < 4; ++e) c[mi][ni][e] = 0.0f;

#pragma unroll
    for (int p = 0; p < 3; ++p) {
        const int ao = (p == 2) ? 256 : 0;
        const int bo = (p == 1) ? 256 : 0;
#pragma unroll
        for (int kk = 0; kk < 16; ++kk) {
            const int kb = kk * 16;
            uint32_t a[2][4];
#pragma unroll
            for (int mi = 0; mi < 2; ++mi) {
                const uint16_t* ap = As + (m0 + mi * 16 + g) * G2_PA + ao + kb + 2 * q;
                a[mi][0] = lds32(ap);
                a[mi][1] = lds32(ap + 8 * G2_PA);
                a[mi][2] = lds32(ap + 8);
                a[mi][3] = lds32(ap + 8 * G2_PA + 8);
            }
#pragma unroll
            for (int ni = 0; ni < 4; ++ni) {
                const uint16_t* bp = Bs + (n0 + ni * 8 + g) * G2_PA + bo + kb + 2 * q;
                uint32_t b0 = lds32(bp), b1 = lds32(bp + 8);
                mma16816(c[0][ni], a[0], b0, b1);
                mma16816(c[1][ni], a[1], b0, b1);
            }
        }
    }

    float* out = Y + (size_t)t * NB * NY;
#pragma unroll
    for (int mi = 0; mi < 2; ++mi) {
#pragma unroll
        for (int ni = 0; ni < 4; ++ni) {
            int r = m0 + mi * 16 + g, n = n0 + ni * 8 + 2 * q;
            float b0 = bias[n], b1 = bias[n + 1];
            *(float2*)&out[(size_t)r * NY + n] =
                make_float2(c[mi][ni][0] + b0, c[mi][ni][1] + b1);
            *(float2*)&out[(size_t)(r + 8) * NY + n] =
                make_float2(c[mi][ni][2] + b0, c[mi][ni][3] + b1);
        }
    }
}

// ---------------- launch ------------------------------------------------------
extern "C" void kernel_launch(void* const* d_in, const int* in_sizes, int n_in,
                              void* d_out, int out_size) {
    const float* y0   = (const float*)d_in[0];
    const float* U    = (const float*)d_in[1];
    const float* lrc  = (const float*)d_in[2];
    const float* lic  = (const float*)d_in[3];
    const float* B    = (const float*)d_in[4];
    const float* Wy2x = (const float*)d_in[5];
    const float* by2x = (const float*)d_in[6];
    const float* Wx2y = (const float*)d_in[7];
    const float* bx2y = (const float*)d_in[8];
    float* Y = (float*)d_out;

    cudaFuncSetAttribute(gemm_bu_mma, cudaFuncAttributeMaxDynamicSharedMemorySize, G1_SMEM);
    cudaFuncSetAttribute(gemm_y_mma,  cudaFuncAttributeMaxDynamicSharedMemorySize, G2_SMEM);

    params_kernel<<<1, 128>>>(lrc, lic);
    prep_kernel<<<64, 256>>>(B, Wx2y);
    x0_kernel<<<NB, 128>>>(y0, Wy2x, by2x);

    gemm_bu_mma<<<T_HRZ, 512, G1_SMEM>>>(U);

    scan_kernel<false><<<NCHUNK * NB * NPAIR / 256, 256>>>();
    carry_kernel<<<NB * NPAIR / 256, 256>>>();
    scan_kernel<true><<<NCHUNK * NB * NPAIR / 256, 256>>>();

    gemm_y_mma<<<T_HRZ, 256, G2_SMEM>>>(bx2y, Y);
}

// round 4
// speedup vs baseline: 2.0281x; 1.2639x over previous
#include <cuda_runtime.h>
#include <cuda_bf16.h>
#include <cstdint>
#include <math.h>

#define T_HRZ 1024
#define NB    128
#define NU    64
#define NY    64
#define NH    256
#define NPAIR 128
#define NCHUNK 16
#define LCHUNK 64

// ---------------- small scratch (no big intermediates!) ----------------------
__device__ float2 g_F[NCHUNK * NB * NPAIR];
__device__ float2 g_S[NCHUNK * NB * NPAIR];
__device__ float  g_lr[NPAIR], g_li[NPAIR], g_nf[NPAIR];
__device__ float2 g_lamL[NPAIR];
// GEMM1 B operand, PAIRED row order n'=2j(re)/2j+1(im), bf16 hi/lo, [256][64]
__device__ __align__(16) uint16_t g_Bph[NH * NU], g_Bpl[NH * NU];
// GEMM2 W operand, k' PERMUTED to paired order, bf16 hi/lo, [64][256]
__device__ __align__(16) uint16_t g_Wph[NY * NH], g_Wpl[NY * NH];

// ---------------- helpers ----------------------------------------------------
__device__ __forceinline__ uint32_t smem_u32(const void* p) {
    uint32_t a;
    asm("{ .reg .u64 t; cvta.to.shared.u64 t, %1; cvt.u32.u64 %0, t; }" : "=r"(a) : "l"(p));
    return a;
}
__device__ __forceinline__ void cvt_hilo(float f, uint16_t& h, uint16_t& l) {
    __nv_bfloat16 hb = __float2bfloat16(f);
    float fh = __bfloat162float(hb);
    __nv_bfloat16 lb = __float2bfloat16(f - fh);
    h = __bfloat16_as_ushort(hb);
    l = __bfloat16_as_ushort(lb);
}
__device__ __forceinline__ void mma16816(float* c, const uint32_t* a,
                                         uint32_t b0, uint32_t b1) {
    asm volatile(
        "mma.sync.aligned.m16n8k16.row.col.f32.bf16.bf16.f32 "
        "{%0,%1,%2,%3}, {%4,%5,%6,%7}, {%8,%9}, {%0,%1,%2,%3};"
        : "+f"(c[0]), "+f"(c[1]), "+f"(c[2]), "+f"(c[3])
        : "r"(a[0]), "r"(a[1]), "r"(a[2]), "r"(a[3]), "r"(b0), "r"(b1));
}
__device__ __forceinline__ void ldsm_x4(uint32_t* r, uint32_t addr) {
    asm volatile("ldmatrix.sync.aligned.m8n8.x4.shared.b16 {%0,%1,%2,%3}, [%4];"
                 : "=r"(r[0]), "=r"(r[1]), "=r"(r[2]), "=r"(r[3]) : "r"(addr));
}
__device__ __forceinline__ void ldsm_x2(uint32_t& r0, uint32_t& r1, uint32_t addr) {
    asm volatile("ldmatrix.sync.aligned.m8n8.x2.shared.b16 {%0,%1}, [%2];"
                 : "=r"(r0), "=r"(r1) : "r"(addr));
}

// ---------------- K0: params --------------------------------------------------
__global__ void params_kernel(const float* __restrict__ lrc, const float* __restrict__ lic) {
    int j = threadIdx.x;
    if (j < NPAIR) {
        float a = fabsf(lrc[j]);
        float r = expf(-a);
        float th = 1.5707963267948966f * lic[j];
        float lr = r * cosf(th), li = r * sinf(th);
        g_lr[j] = lr; g_li[j] = li;
        g_nf[j] = sqrtf(1.0f - expf(-2.0f * a));
        float wr = 1.0f, wi = 0.0f;
        for (int l = 0; l < LCHUNK; ++l) {
            float nr = wr * lr - wi * li;
            wi = wr * li + wi * lr; wr = nr;
        }
        g_lamL[j] = make_float2(wr, wi);
    }
}

// ---------------- K0b: operand prep -------------------------------------------
__global__ void prep_kernel(const float* __restrict__ B, const float* __restrict__ W) {
    int i = blockIdx.x * 256 + threadIdx.x;   // 16384 for both tables
    if (i < NH * NU) {
        int np = i >> 6, k = i & 63;
        int j = np >> 1, p = np & 1;
        float v = B[(size_t)(j + p * NPAIR) * NU + k] * g_nf[j];
        cvt_hilo(v, g_Bph[i], g_Bpl[i]);
    }
    if (i < NY * NH) {
        int n = i >> 8, kk = i & 255;
        int j = kk >> 1, p = kk & 1;
        cvt_hilo(W[(size_t)n * NH + j + p * NPAIR], g_Wph[i], g_Wpl[i]);
    }
}

// ---------------- K3a: x0 = y0 @ Wy2x^T + b -----------------------------------
__global__ void __launch_bounds__(128) x0_kernel(const float* __restrict__ y0,
                                                 const float* __restrict__ W,
                                                 const float* __restrict__ bias) {
    __shared__ float Ws[128 * 65];
    __shared__ float ys[64];
    int b = blockIdx.x, tid = threadIdx.x;
    if (tid < 64) ys[tid] = y0[(size_t)b * NY + tid];
    float xr = 0.0f, xi = 0.0f;
#pragma unroll
    for (int half = 0; half < 2; ++half) {
        const float4* src = (const float4*)(W + (size_t)half * 128 * NY);
        for (int i = tid; i < 2048; i += 128) {
            float4 v = src[i];
            int r = i >> 4, cc = (i & 15) * 4;
            float* d = &Ws[r * 65 + cc];
            d[0] = v.x; d[1] = v.y; d[2] = v.z; d[3] = v.w;
        }
        __syncthreads();
        float acc = bias[tid + half * 128];
        const float* w = &Ws[tid * 65];
#pragma unroll
        for (int y = 0; y < NY; ++y) acc = fmaf(ys[y], w[y], acc);
        if (half == 0) xr = acc; else xi = acc;
        __syncthreads();
    }
    g_S[b * NPAIR + tid] = make_float2(xr, xi);
}

// ---------------- K3b: carry scan ---------------------------------------------
__global__ void __launch_bounds__(256) carry_kernel() {
    int gtid = blockIdx.x * 256 + threadIdx.x;   // 16384
    int j = gtid & (NPAIR - 1);
    int b = gtid >> 7;
    float2 f[NCHUNK - 1];
#pragma unroll
    for (int c = 0; c < NCHUNK - 1; ++c) f[c] = g_F[(c * NB + b) * NPAIR + j];
    float2 s = g_S[b * NPAIR + j];
    float2 w = g_lamL[j];
    float xr = s.x, xi = s.y;
#pragma unroll
    for (int c = 1; c < NCHUNK; ++c) {
        float nr = fmaf(w.x, xr, fmaf(-w.y, xi, f[c - 1].x));
        float ni = fmaf(w.y, xr, fmaf(w.x, xi, f[c - 1].y));
        xr = nr; xi = ni;
        g_S[(c * NB + b) * NPAIR + j] = make_float2(xr, xi);
    }
}

// ===================== fused kernels ==========================================
// Common geometry: block = (chunk c, batch tile of 16), 256 threads = 8 warps.
// GEMM1 per t: A = U[t, b0:b0+16, :] (m16 k64), B = paired Bs (n256 k64),
//   warp w owns n-cols [w*32, w*32+32) = 4 n-frags; 3-term bf16 split.
// Scan state lives in the C-fragment thread mapping:
//   thread (g,q), frag f, row r: b = b0+g+8r, j = w*16 + f*4 + q.

#define PA 136                      // G1 smem row pitch (halves): 64 hi | 64 lo | 8 pad
#define PX 520                      // G2 smem row pitch (halves): 256 hi | 256 lo | 8 pad
#define BS_BYTES (256 * PA * 2)     // 69632
#define UB_BYTES (2 * 16 * PA * 2)  // 8704
#define WP_BYTES (64 * PX * 2)      // 66560
#define XT_BYTES (16 * PX * 2)      // 16640

#define KA_SMEM (BS_BYTES + UB_BYTES)
#define KB_SMEM (BS_BYTES + WP_BYTES + XT_BYTES + UB_BYTES)

// fill Bs (paired bf16 hi/lo) into pitched smem
__device__ __forceinline__ void fill_Bs(uint16_t* Bs, int tid) {
#pragma unroll
    for (int it = 0; it < 8; ++it) {
        int i = it * 256 + tid;            // 2048 uint4 per plane
        int n = i >> 3, k8 = (i & 7) * 8;
        *(uint4*)&Bs[n * PA + k8]      = ((const uint4*)g_Bph)[i];
        *(uint4*)&Bs[n * PA + 64 + k8] = ((const uint4*)g_Bpl)[i];
    }
}
// store one thread's U float4 into Ubuf (hi/lo)
__device__ __forceinline__ void store_U(uint16_t* Ub, int buf, int row, int k4, float4 v) {
    uint16_t h0,l0,h1,l1,h2,l2,h3,l3;
    cvt_hilo(v.x,h0,l0); cvt_hilo(v.y,h1,l1); cvt_hilo(v.z,h2,l2); cvt_hilo(v.w,h3,l3);
    uint16_t* p = Ub + buf * 16 * PA + row * PA;
    *(uint2*)&p[k4]      = make_uint2(h0 | ((uint32_t)h1 << 16), h2 | ((uint32_t)h3 << 16));
    *(uint2*)&p[64 + k4] = make_uint2(l0 | ((uint32_t)l1 << 16), l2 | ((uint32_t)l3 << 16));
}

// GEMM1 step: accumulate C[4][4] (4 n-frags) for current Ubuf buffer
__device__ __forceinline__ void g1_mma(float C[4][4], uint32_t sU, uint32_t sB,
                                       int buf, int lane, int n0) {
    const int r8 = lane & 7;
    // A ldmatrix lane offsets: sel bit0 -> row+8, bit1 -> col+8
    const uint32_t aRow = (uint32_t)(buf * 16 * PA + (r8 + ((lane >> 3) & 1) * 8) * PA) * 2;
    const uint32_t aCol = (uint32_t)(((lane >> 4) & 1) * 8) * 2;
    // B ldmatrix: sel bit0 -> col+8, bit1 -> frag row +8
    const uint32_t bRowBase = (uint32_t)((n0 + r8 + ((lane >> 4) & 1) * 8) * PA) * 2;
    const uint32_t bCol = (uint32_t)(((lane >> 3) & 1) * 8) * 2;
#pragma unroll
    for (int ks = 0; ks < 4; ++ks) {
        const uint32_t kb = ks * 32;   // bytes (16 halves)
        uint32_t ah[4], al[4];
        ldsm_x4(ah, sU + aRow + aCol + kb);
        ldsm_x4(al, sU + aRow + aCol + kb + 128);   // +64 halves
#pragma unroll
        for (int fp = 0; fp < 2; ++fp) {
            uint32_t bh[4], bl[4];
            uint32_t ro = bRowBase + (uint32_t)(fp * 16 * PA) * 2;
            ldsm_x4(bh, sB + ro + bCol + kb);
            ldsm_x4(bl, sB + ro + bCol + kb + 128);
            mma16816(C[fp*2],   ah, bh[0], bh[1]);
            mma16816(C[fp*2],   ah, bl[0], bl[1]);
            mma16816(C[fp*2],   al, bh[0], bh[1]);
            mma16816(C[fp*2+1], ah, bh[2], bh[3]);
            mma16816(C[fp*2+1], ah, bl[2], bl[3]);
            mma16816(C[fp*2+1], al, bh[2], bh[3]);
        }
    }
}

// ---------------- K_A: fused GEMM1 + scan pass A ------------------------------
__global__ void __launch_bounds__(256, 1) fused_passA(const float* __restrict__ U) {
    extern __shared__ char smem[];
    uint16_t* Bs = (uint16_t*)smem;
    uint16_t* Ub = (uint16_t*)(smem + BS_BYTES);
    const uint32_t sB = smem_u32(Bs), sU = smem_u32(Ub);
    const int tid = threadIdx.x, wid = tid >> 5, lane = tid & 31;
    const int g = lane >> 2, q = lane & 3;
    const int c = blockIdx.x >> 3, bt = blockIdx.x & 7;
    const int b0 = bt * 16, n0 = wid * 32;

    fill_Bs(Bs, tid);

    float ar[4], ai[4];
#pragma unroll
    for (int f = 0; f < 4; ++f) {
        int j = wid * 16 + f * 4 + q;
        ar[f] = g_lr[j]; ai[f] = g_li[j];
    }
    float xr[4][2], xi[4][2];
#pragma unroll
    for (int f = 0; f < 4; ++f) { xr[f][0]=xr[f][1]=0.f; xi[f][0]=xi[f][1]=0.f; }

    const int urow = tid >> 4, uk4 = (tid & 15) * 4;
    const float* up = U + ((size_t)(c * LCHUNK) * NB + b0 + urow) * NU + uk4;
    const size_t ustep = (size_t)NB * NU;
    store_U(Ub, 0, urow, uk4, *(const float4*)up);
    __syncthreads();

#pragma unroll 1
    for (int lt = 0; lt < LCHUNK; ++lt) {
        float4 un;
        if (lt + 1 < LCHUNK) un = *(const float4*)(up + (lt + 1) * ustep);
        float C[4][4];
#pragma unroll
        for (int f = 0; f < 4; ++f)
#pragma unroll
            for (int e = 0; e < 4; ++e) C[f][e] = 0.0f;

        g1_mma(C, sU, sB, lt & 1, lane, n0);

#pragma unroll
        for (int f = 0; f < 4; ++f)
#pragma unroll
            for (int r = 0; r < 2; ++r) {
                float cre = C[f][r*2], cim = C[f][r*2+1];
                float nr = fmaf(ar[f], xr[f][r], fmaf(-ai[f], xi[f][r], cre));
                float ni = fmaf(ai[f], xr[f][r], fmaf( ar[f], xi[f][r], cim));
                xr[f][r] = nr; xi[f][r] = ni;
            }
        if (lt + 1 < LCHUNK) store_U(Ub, (lt + 1) & 1, urow, uk4, un);
        __syncthreads();
    }
    // write chunk finals
#pragma unroll
    for (int f = 0; f < 4; ++f)
#pragma unroll
        for (int r = 0; r < 2; ++r) {
            int b = b0 + g + r * 8;
            int j = wid * 16 + f * 4 + q;
            g_F[(c * NB + b) * NPAIR + j] = make_float2(xr[f][r], xi[f][r]);
        }
}

// ---------------- K_B: fused GEMM1 + scan pass B + GEMM2 ----------------------
__global__ void __launch_bounds__(256, 1) fused_passB(const float* __restrict__ U,
                                                      const float* __restrict__ bias,
                                                      float* __restrict__ Y) {
    extern __shared__ char smem[];
    uint16_t* Bs = (uint16_t*)smem;
    uint16_t* Wp = (uint16_t*)(smem + BS_BYTES);
    uint16_t* Xt = (uint16_t*)(smem + BS_BYTES + WP_BYTES);
    uint16_t* Ub = (uint16_t*)(smem + BS_BYTES + WP_BYTES + XT_BYTES);
    const uint32_t sB = smem_u32(Bs), sW = smem_u32(Wp);
    const uint32_t sX = smem_u32(Xt), sU = smem_u32(Ub);
    const int tid = threadIdx.x, wid = tid >> 5, lane = tid & 31;
    const int g = lane >> 2, q = lane & 3;
    const int c = blockIdx.x >> 3, bt = blockIdx.x & 7;
    const int b0 = bt * 16, n0 = wid * 32, n0y = wid * 8;

    fill_Bs(Bs, tid);
#pragma unroll
    for (int it = 0; it < 8; ++it) {
        int i = it * 256 + tid;            // 2048 uint4 per plane
        int n = i >> 5, k8 = (i & 31) * 8;
        *(uint4*)&Wp[n * PX + k8]       = ((const uint4*)g_Wph)[i];
        *(uint4*)&Wp[n * PX + 256 + k8] = ((const uint4*)g_Wpl)[i];
    }

    float ar[4], ai[4], xr[4][2], xi[4][2];
#pragma unroll
    for (int f = 0; f < 4; ++f) {
        int j = wid * 16 + f * 4 + q;
        ar[f] = g_lr[j]; ai[f] = g_li[j];
#pragma unroll
        for (int r = 0; r < 2; ++r) {
            int b = b0 + g + r * 8;
            float2 s = g_S[(c * NB + b) * NPAIR + j];
            xr[f][r] = s.x; xi[f][r] = s.y;
        }
    }
    const float by0 = bias[n0y + 2 * q], by1 = bias[n0y + 2 * q + 1];

    const int urow = tid >> 4, uk4 = (tid & 15) * 4;
    const float* up = U + ((size_t)(c * LCHUNK) * NB + b0 + urow) * NU + uk4;
    const size_t ustep = (size_t)NB * NU;
    store_U(Ub, 0, urow, uk4, *(const float4*)up);
    __syncthreads();

    // G2 ldmatrix lane offsets (A from Xt; B from Wp)
    const int r8 = lane & 7;
    const uint32_t xRow = (uint32_t)((r8 + ((lane >> 3) & 1) * 8) * PX) * 2;
    const uint32_t xCol = (uint32_t)(((lane >> 4) & 1) * 8) * 2;
    const uint32_t wRow = (uint32_t)((n0y + r8) * PX) * 2;
    const uint32_t wCol = (uint32_t)(((lane >> 3) & 1) * 8) * 2;

#pragma unroll 1
    for (int lt = 0; lt < LCHUNK; ++lt) {
        float4 un;
        if (lt + 1 < LCHUNK) un = *(const float4*)(up + (lt + 1) * ustep);

        float C[4][4];
#pragma unroll
        for (int f = 0; f < 4; ++f)
#pragma unroll
            for (int e = 0; e < 4; ++e) C[f][e] = 0.0f;

        g1_mma(C, sU, sB, lt & 1, lane, n0);

        // scan update + write X tile (bf16 hi/lo, paired k' order)
#pragma unroll
        for (int f = 0; f < 4; ++f)
#pragma unroll
            for (int r = 0; r < 2; ++r) {
                float cre = C[f][r*2], cim = C[f][r*2+1];
                float nr = fmaf(ar[f], xr[f][r], fmaf(-ai[f], xi[f][r], cre));
                float ni = fmaf(ai[f], xr[f][r], fmaf( ar[f], xi[f][r], cim));
                xr[f][r] = nr; xi[f][r] = ni;
                uint16_t hr, lr_, hi_, li_;
                cvt_hilo(nr, hr, lr_); cvt_hilo(ni, hi_, li_);
                int row = g + r * 8;
                int col = n0 + f * 8 + 2 * q;
                *(uint32_t*)&Xt[row * PX + col]       = hr  | ((uint32_t)hi_ << 16);
                *(uint32_t*)&Xt[row * PX + 256 + col] = lr_ | ((uint32_t)li_ << 16);
            }
        if (lt + 1 < LCHUNK) store_U(Ub, (lt + 1) & 1, urow, uk4, un);
        __syncthreads();

        // GEMM2: Y[t, b-tile, :] = Xt @ Wp^T
        float C2[4] = {0.f, 0.f, 0.f, 0.f};
#pragma unroll
        for (int ks = 0; ks < 16; ++ks) {
            const uint32_t kb = ks * 32;   // bytes
            uint32_t ah[4], al[4];
            ldsm_x4(ah, sX + xRow + xCol + kb);
            ldsm_x4(al, sX + xRow + xCol + kb + 512);   // +256 halves
            uint32_t bh0, bh1, bl0, bl1;
            ldsm_x2(bh0, bh1, sW + wRow + wCol + kb);
            ldsm_x2(bl0, bl1, sW + wRow + wCol + kb + 512);
            mma16816(C2, ah, bh0, bh1);
            mma16816(C2, ah, bl0, bl1);
            mma16816(C2, al, bh0, bh1);
        }
        const int gt = c * LCHUNK + lt;
        float* y0p = Y + ((size_t)gt * NB + b0 + g) * NY + n0y + 2 * q;
        *(float2*)y0p = make_float2(C2[0] + by0, C2[1] + by1);
        *(float2*)(y0p + 8 * NY) = make_float2(C2[2] + by0, C2[3] + by1);
        __syncthreads();
    }
}

// ---------------- launch ------------------------------------------------------
extern "C" void kernel_launch(void* const* d_in, const int* in_sizes, int n_in,
                              void* d_out, int out_size) {
    const float* y0   = (const float*)d_in[0];
    const float* U    = (const float*)d_in[1];
    const float* lrc  = (const float*)d_in[2];
    const float* lic  = (const float*)d_in[3];
    const float* B    = (const float*)d_in[4];
    const float* Wy2x = (const float*)d_in[5];
    const float* by2x = (const float*)d_in[6];
    const float* Wx2y = (const float*)d_in[7];
    const float* bx2y = (const float*)d_in[8];
    float* Y = (float*)d_out;

    cudaFuncSetAttribute(fused_passA, cudaFuncAttributeMaxDynamicSharedMemorySize, KA_SMEM);
    cudaFuncSetAttribute(fused_passB, cudaFuncAttributeMaxDynamicSharedMemorySize, KB_SMEM);

    params_kernel<<<1, 128>>>(lrc, lic);
    prep_kernel<<<64, 256>>>(B, Wx2y);
    x0_kernel<<<NB, 128>>>(y0, Wy2x, by2x);

    fused_passA<<<NCHUNK * 8, 256, KA_SMEM>>>(U);
    carry_kernel<<<NB * NPAIR / 256, 256>>>();
    fused_passB<<<NCHUNK * 8, 256, KB_SMEM>>>(U, bx2y, Y);
}